// round 1
// baseline (speedup 1.0000x reference)
#include <cuda_runtime.h>
#include <cstdint>

// out[b,i,j] = x[b, i, i+j] if i+j < L else 0
// B=4, L=4096, LIMIT=256
#define MAXLEN 4096
#define LIMIT  256
#define BATCH  4

__global__ __launch_bounds__(256)
void band_gather_kernel(const float* __restrict__ x, float* __restrict__ out)
{
    // Each thread produces 4 consecutive output elements (one float4 store).
    // gid indexes over BATCH*MAXLEN*(LIMIT/4) float4 outputs.
    const int gid = blockIdx.x * blockDim.x + threadIdx.x;

    const int J4   = LIMIT / 4;              // 64 float4 per row
    const int row  = gid / J4;               // b*L + i  (0 .. BATCH*MAXLEN)
    const int j0   = (gid - row * J4) * 4;   // starting j within the band
    const int i    = row & (MAXLEN - 1);     // row within the batch matrix

    const float* __restrict__ src = x + (size_t)row * MAXLEN;
    const int c0 = i + j0;                   // source column of first element

    float4 v;
    v.x = (c0 + 0 < MAXLEN) ? __ldg(src + c0 + 0) : 0.0f;
    v.y = (c0 + 1 < MAXLEN) ? __ldg(src + c0 + 1) : 0.0f;
    v.z = (c0 + 2 < MAXLEN) ? __ldg(src + c0 + 2) : 0.0f;
    v.w = (c0 + 3 < MAXLEN) ? __ldg(src + c0 + 3) : 0.0f;

    reinterpret_cast<float4*>(out)[gid] = v;
}

extern "C" void kernel_launch(void* const* d_in, const int* in_sizes, int n_in,
                              void* d_out, int out_size)
{
    (void)in_sizes; (void)n_in; (void)out_size;
    const float* x = (const float*)d_in[0];
    float* out = (float*)d_out;

    const int total_vec4 = BATCH * MAXLEN * (LIMIT / 4);  // 1,048,576
    const int threads = 256;
    const int blocks = total_vec4 / threads;              // 4096

    band_gather_kernel<<<blocks, threads>>>(x, out);
}